// round 5
// baseline (speedup 1.0000x reference)
#include <cuda_runtime.h>
#include <math.h>

#define Hh 1024
#define Ww 1024
#define Cc 16
#define HW (1024*1024)

#define ZD (-0.26794919243112270647)   // sqrt(3) - 2

static __device__ float  g_tmp[Cc*HW];    // row-filtered image
static __device__ float  g_coef[Cc*HW];   // fully prefiltered image coefficients
static __device__ float  g_dcoef[18];     // prefiltered control-point displacements (2x3x3)
static __device__ float4 g_wy4[1024];     // strict cubic weights per coordinate
static __device__ int    g_myp[1024];     // packed mirrored indices (2 bits x 4)
static __device__ float  g_R[6*1024];     // folded x-dir displacement rows [ch*3+j][x]
static __device__ float2 g_field[HW];     // (sy, sx) per pixel

// --- exact reference 3-point spline_filter1d (horizon = 3), eager-mode fp32 --
__device__ __forceinline__ void filt3(float v0, float v1, float v2, float* o) {
    const float Zf    = (float)ZD;
    const float Z2f   = (float)(ZD*ZD);
    const float GAIN  = 6.0f;                      // (1-z)(1-1/z) = 6 exactly
    const float LASTC = (float)(ZD/(ZD*ZD-1.0));
    float c0 = __fmul_rn(v0, GAIN);
    float c1 = __fmul_rn(v1, GAIN);
    float c2 = __fmul_rn(v2, GAIN);
    float cp0 = c0;
    cp0 = __fmaf_rn(Zf,  c1, cp0);
    cp0 = __fmaf_rn(Z2f, c2, cp0);
    float cp1 = __fadd_rn(c1, __fmul_rn(Zf, cp0));
    float cp2 = __fadd_rn(c2, __fmul_rn(Zf, cp1));
    float last = __fmul_rn(LASTC, __fadd_rn(cp2, __fmul_rn(Zf, cp1)));
    float o1 = __fmul_rn(Zf, __fsub_rn(last, cp1));
    float o0 = __fmul_rn(Zf, __fsub_rn(o1,  cp0));
    o[0] = o0; o[1] = o1; o[2] = last;
}

__global__ void setup_kernel(const float* __restrict__ disp) {
    if (threadIdx.x == 0) {
        float d[2][3][3];
        for (int ch = 0; ch < 2; ch++)
            for (int i = 0; i < 3; i++)
                for (int j = 0; j < 3; j++)
                    d[ch][i][j] = __fmul_rn(disp[ch*9 + i*3 + j], 10.0f);   // SIGMA
        for (int ch = 0; ch < 2; ch++)
            for (int j = 0; j < 3; j++) {
                float o[3];
                filt3(d[ch][0][j], d[ch][1][j], d[ch][2][j], o);
                d[ch][0][j] = o[0]; d[ch][1][j] = o[1]; d[ch][2][j] = o[2];
            }
        for (int ch = 0; ch < 2; ch++)
            for (int i = 0; i < 3; i++) {
                float o[3];
                filt3(d[ch][i][0], d[ch][i][1], d[ch][i][2], o);
                g_dcoef[ch*9 + i*3 + 0] = o[0];
                g_dcoef[ch*9 + i*3 + 1] = o[1];
                g_dcoef[ch*9 + i*3 + 2] = o[2];
            }
    }
}

// --- strict (eager-jax) cubic weights: exact primitive-by-primitive ----------
__device__ __forceinline__ void cubw_strict(float f, float* w) {
    float f2 = __fmul_rn(f, f);
    float f3 = __fmul_rn(f2, f);
    float t = __fsub_rn(1.0f, __fmul_rn(3.0f, f));
    t = __fadd_rn(t, __fmul_rn(3.0f, f2));
    t = __fsub_rn(t, f3);
    w[0] = __fdiv_rn(t, 6.0f);
    t = __fsub_rn(4.0f, __fmul_rn(6.0f, f2));
    t = __fadd_rn(t, __fmul_rn(3.0f, f3));
    w[1] = __fdiv_rn(t, 6.0f);
    t = __fadd_rn(1.0f, __fmul_rn(3.0f, f));
    t = __fadd_rn(t, __fmul_rn(3.0f, f2));
    t = __fsub_rn(t, __fmul_rn(3.0f, f3));
    w[2] = __fdiv_rn(t, 6.0f);
    w[3] = __fdiv_rn(f3, 6.0f);
}

__device__ __forceinline__ int mir3(int i) {        // mirror, n=3 (period 4)
    int m = i < 0 ? -i : i;
    m &= 3;
    return m > 2 ? 4 - m : m;
}
__device__ __forceinline__ int refl1024(int i) {    // mirror, n=1024 (small excursions)
    return i < 0 ? -i : (i > 1023 ? 2046 - i : i);
}

// --- per-coordinate strict weight tables + folded displacement rows ----------
__global__ void table_kernel() {
    int i = blockIdx.x * 256 + threadIdx.x;         // coordinate 0..1023
    const float SCL = (float)(2.0/1023.0);
    float u = __fmul_rn((float)i, SCL);
    float fl = floorf(u); int i0 = (int)fl;
    float f = __fsub_rn(u, fl);
    float w[4];
    cubw_strict(f, w);
    int m[4];
    #pragma unroll
    for (int b = 0; b < 4; b++) m[b] = mir3(i0 + b - 1);
    g_wy4[i] = make_float4(w[0], w[1], w[2], w[3]);
    g_myp[i] = m[0] | (m[1] << 2) | (m[2] << 4) | (m[3] << 6);
    // fold x-weights into displacement rows with EXACT reference op order
    #pragma unroll
    for (int ch = 0; ch < 2; ch++)
        #pragma unroll
        for (int j = 0; j < 3; j++) {
            float r = 0.0f;
            #pragma unroll
            for (int b = 0; b < 4; b++)
                r = __fadd_rn(r, __fmul_rn(w[b], g_dcoef[ch*9 + j*3 + m[b]]));
            g_R[(ch*3 + j)*1024 + i] = r;
        }
}

// --- field+mask kernel: strict (sy, sx) per pixel, then nearest mask gather --
__global__ void __launch_bounds__(256) field_mask_kernel(const float* __restrict__ mask,
                                                         float* __restrict__ out) {
    int x = blockIdx.x * 256 + threadIdx.x;
    int y = blockIdx.y;
    float4 wy = g_wy4[y];
    int mp = g_myp[y];
    const float* Rx = g_R + x;
    float d0 = 0.0f, d1 = 0.0f;
    int j;
    j = mp & 3;
    d0 = __fadd_rn(d0, __fmul_rn(wy.x, __ldg(Rx + j*1024)));
    d1 = __fadd_rn(d1, __fmul_rn(wy.x, __ldg(Rx + (3+j)*1024)));
    j = (mp >> 2) & 3;
    d0 = __fadd_rn(d0, __fmul_rn(wy.y, __ldg(Rx + j*1024)));
    d1 = __fadd_rn(d1, __fmul_rn(wy.y, __ldg(Rx + (3+j)*1024)));
    j = (mp >> 4) & 3;
    d0 = __fadd_rn(d0, __fmul_rn(wy.z, __ldg(Rx + j*1024)));
    d1 = __fadd_rn(d1, __fmul_rn(wy.z, __ldg(Rx + (3+j)*1024)));
    j = (mp >> 6) & 3;
    d0 = __fadd_rn(d0, __fmul_rn(wy.w, __ldg(Rx + j*1024)));
    d1 = __fadd_rn(d1, __fmul_rn(wy.w, __ldg(Rx + (3+j)*1024)));
    float sy = __fadd_rn((float)y, d0);
    float sx = __fadd_rn((float)x, d1);
    int oidx = y*Ww + x;
    g_field[oidx] = make_float2(sy, sx);

    bool valid = (sy >= 0.0f) && (sy <= 1023.0f) && (sx >= 0.0f) && (sx <= 1023.0f);
    if (valid) {
        int ny = (int)rintf(sy); ny = ny < 0 ? 0 : (ny > 1023 ? 1023 : ny);  // half-even
        int nx = (int)rintf(sx); nx = nx < 0 ? 0 : (nx > 1023 ? 1023 : nx);
        int midx = ny*Ww + nx;
        #pragma unroll
        for (int c = 0; c < Cc; c++)
            out[(Cc + c)*HW + oidx] = __ldg(mask + c*HW + midx);
    } else {
        #pragma unroll
        for (int c = 0; c < Cc; c++)
            out[(Cc + c)*HW + oidx] = 0.0f;
    }
}

// --- row prefilter (along x): warp per row, shuffle scan ---------------------
// Self-contained: per-thread z powers computed locally (no global-table race).
__global__ void __launch_bounds__(256) rowfilt_kernel(const float* __restrict__ img) {
    int warp = blockIdx.x * 8 + (threadIdx.x >> 5);   // 0 .. 16383  (c*1024 + y)
    int lane = threadIdx.x & 31;
    const float* row = img + warp * Ww;
    float* orow = g_tmp + warp * Ww;

    const float z1  = (float)ZD;
    const float z2  = (float)(ZD*ZD);
    const float z4  = (float)(ZD*ZD*ZD*ZD);
    const float z8  = (float)(ZD*ZD*ZD*ZD*ZD*ZD*ZD*ZD);
    const float z16 = z8*z8;
    const float SQ3 = (float)((1.0-ZD)/(1.0+ZD));   // sqrt(3)

    // per-thread z powers in double (matches prior table exactly)
    double zd = 1.0;
    for (int i = 0; i < lane; i++) zd *= ZD;
    float zl0 = (float)zd;           // z^lane
    float zl1 = (float)(zd * ZD);    // z^(lane+1)
    double zrd = 1.0;
    for (int i = 0; i < 32 - lane; i++) zrd *= ZD;
    float zr = (float)zrd;           // z^(32-lane)

    float xs[32], As[32];
    float carry = 0.0f;

    #pragma unroll
    for (int b = 0; b < 32; b++) {
        float x = row[b*32 + lane];
        xs[b] = x;
        float a = x, v;
        v = __shfl_up_sync(0xffffffffu, a, 1);  if (lane >= 1)  a += z1  * v;
        v = __shfl_up_sync(0xffffffffu, a, 2);  if (lane >= 2)  a += z2  * v;
        v = __shfl_up_sync(0xffffffffu, a, 4);  if (lane >= 4)  a += z4  * v;
        v = __shfl_up_sync(0xffffffffu, a, 8);  if (lane >= 8)  a += z8  * v;
        v = __shfl_up_sync(0xffffffffu, a, 16); if (lane >= 16) a += z16 * v;
        a += zl1 * carry;
        carry = __shfl_sync(0xffffffffu, a, 31);
        As[b] = a;
    }
    float A1022 = __shfl_sync(0xffffffffu, As[31], 30);

    float carryR = 0.0f;
    #pragma unroll
    for (int b = 31; b >= 0; b--) {
        float x = xs[b];
        float r = x, v;
        v = __shfl_down_sync(0xffffffffu, r, 1);  if (lane < 31) r += z1  * v;
        v = __shfl_down_sync(0xffffffffu, r, 2);  if (lane < 30) r += z2  * v;
        v = __shfl_down_sync(0xffffffffu, r, 4);  if (lane < 28) r += z4  * v;
        v = __shfl_down_sync(0xffffffffu, r, 8);  if (lane < 24) r += z8  * v;
        v = __shfl_down_sync(0xffffffffu, r, 16); if (lane < 16) r += z16 * v;
        r += zr * carryR;
        carryR = __shfl_sync(0xffffffffu, r, 0);
        float d = r - x;
        float t = As[b] + d;
        if (b == 31) t += zr * A1022;
        if (b == 0) {
            float B0 = __shfl_sync(0xffffffffu, d, 0);
            t += zl0 * B0;
        }
        orow[b*32 + lane] = SQ3 * t;
    }
}

// --- column prefilter (along y): register chunks + halo warm-up -------------
__global__ void __launch_bounds__(256) colfilt_kernel() {
    int x  = blockIdx.x * 256 + threadIdx.x;
    int c  = blockIdx.z;
    int ys = blockIdx.y * 32;
    const float* base = g_tmp + c * HW;
    float* ob = g_coef + c * HW;
    const float Zf  = (float)ZD;
    const float SQ3 = (float)((1.0-ZD)/(1.0+ZD));

    float A = 0.0f;
    #pragma unroll
    for (int j = 16; j >= 1; j--) {
        int yy = ys - j; yy = yy < 0 ? -yy : yy;
        A = fmaf(Zf, A, base[yy*Ww + x]);
    }
    float xs[32], As[32];
    #pragma unroll
    for (int j = 0; j < 32; j++) {
        float v = base[(ys + j)*Ww + x];
        A = fmaf(Zf, A, v);
        xs[j] = v; As[j] = A;
    }
    float R = 0.0f;
    #pragma unroll
    for (int j = 15; j >= 0; j--) {
        int yy = ys + 32 + j; yy = yy > 1023 ? 2046 - yy : yy;
        R = fmaf(Zf, R, base[yy*Ww + x]);
    }
    #pragma unroll
    for (int j = 31; j >= 0; j--) {
        ob[(ys + j)*Ww + x] = SQ3 * fmaf(Zf, R, As[j]);
        R = fmaf(Zf, R, xs[j]);
    }
}

// fast weights for the image gather (loose tolerance path)
__device__ __forceinline__ void cubw_fast(float f, float* w) {
    float f2 = f*f;
    float f3 = f2*f;
    const float S = 1.0f/6.0f;
    w[0] = (1.0f - 3.0f*f + 3.0f*f2 - f3) * S;
    w[1] = (4.0f - 6.0f*f2 + 3.0f*f3) * S;
    w[2] = (1.0f + 3.0f*f + 3.0f*f2 - 3.0f*f3) * S;
    w[3] = f3 * S;
}

// --- image eval: cubic gather, 16 channels -----------------------------------
__global__ void __launch_bounds__(256) eval_img_kernel(float* __restrict__ out) {
    int x = blockIdx.x * 256 + threadIdx.x;
    int y = blockIdx.y;
    int oidx = y*Ww + x;
    float2 f = g_field[oidx];
    float sy = f.x, sx = f.y;
    bool valid = (sy >= 0.0f) && (sy <= 1023.0f) && (sx >= 0.0f) && (sx <= 1023.0f);
    if (valid) {
        float fs = floorf(sy); int iy = (int)fs; float fy = sy - fs;
        float gs = floorf(sx); int ix = (int)gs; float fx = sx - gs;
        float Wy[4], Wx[4];
        cubw_fast(fy, Wy); cubw_fast(fx, Wx);
        int ry[4], rx[4];
        #pragma unroll
        for (int a = 0; a < 4; a++) ry[a] = refl1024(iy + a - 1) * Ww;
        #pragma unroll
        for (int b = 0; b < 4; b++) rx[b] = refl1024(ix + b - 1);

        #pragma unroll
        for (int c = 0; c < Cc; c++) {
            const float* p = g_coef + c * HW;
            float s = 0.0f;
            #pragma unroll
            for (int a = 0; a < 4; a++) {
                const float* pr = p + ry[a];
                float row;
                row = Wx[0] * __ldg(pr + rx[0]);
                row = fmaf(Wx[1], __ldg(pr + rx[1]), row);
                row = fmaf(Wx[2], __ldg(pr + rx[2]), row);
                row = fmaf(Wx[3], __ldg(pr + rx[3]), row);
                s = fmaf(Wy[a], row, s);
            }
            out[c*HW + oidx] = s;
        }
    } else {
        #pragma unroll
        for (int c = 0; c < Cc; c++)
            out[c*HW + oidx] = 0.0f;
    }
}

extern "C" void kernel_launch(void* const* d_in, const int* in_sizes, int n_in,
                              void* d_out, int out_size) {
    const float* image = (const float*)d_in[0];
    const float* mask  = (const float*)d_in[1];
    const float* disp  = (const float*)d_in[2];
    float* out = (float*)d_out;

    static cudaStream_t s1 = 0;
    static cudaEvent_t ev0 = 0, ev1 = 0;
    if (s1 == 0) {
        cudaStreamCreateWithFlags(&s1, cudaStreamNonBlocking);
        cudaEventCreateWithFlags(&ev0, cudaEventDisableTiming);
        cudaEventCreateWithFlags(&ev1, cudaEventDisableTiming);
    }

    // fork: prefilter chain on s1 — fully independent of displacement path
    cudaEventRecord(ev0, 0);
    cudaStreamWaitEvent(s1, ev0, 0);
    rowfilt_kernel<<<2048, 256, 0, s1>>>(image);
    colfilt_kernel<<<dim3(4, 32, 16), 256, 0, s1>>>();
    cudaEventRecord(ev1, s1);

    // main stream: displacement path + mask (overlaps with prefilter)
    setup_kernel<<<1, 32>>>(disp);
    table_kernel<<<4, 256>>>();
    field_mask_kernel<<<dim3(4, 1024), 256>>>(mask, out);

    // join: image eval needs coefficients
    cudaStreamWaitEvent(0, ev1, 0);
    eval_img_kernel<<<dim3(4, 1024), 256>>>(out);
}